// round 9
// baseline (speedup 1.0000x reference)
#include <cuda_runtime.h>
#include <cstdint>

// ShoeboxToRIR — round 9: round-8 cluster design + REQUIRED trailing cluster
// sync (a CTA must not exit while its peer still reads its SMEM via DSMEM —
// this omission was round 8's "unspecified launch failure").
//
// grid 512 = (batch 256) x (image-half 2); cluster pairs (2b, 2b+1).
// 384 threads = 3 sub-blocks of 128, each with a private padded smem RIR
// copy covering ~261 images of this CTA's half. Thread t owns samples
// == t (mod 128). After accumulation: reduce 3 copies -> copy 0,
// barrier.cluster (release/acquire), then each CTA writes half the output
// row combining its copy 0 with the peer's over DSMEM, then final cluster
// sync before exit. Deterministic (fixed addition order).

#define NIMG    1561
#define NHALF   781          // images in half 0 (half 1 has 780)
#define NBATCH  256
#define RIRLEN  8000
#define NS      3
#define NTH     (NS * 128)
#define COPYLEN 8256         // 48 lower pad + 8000 + 208 upper pad (floats)
#define LOWPAD  48
#define PADK    40

struct GTab { int v[NIMG]; };
static constexpr int cabs_(int x) { return x < 0 ? -x : x; }
static constexpr GTab make_gtab() {
    GTab g{}; int s = 0;
    for (int x = -10; x <= 10; ++x)
        for (int y = -10; y <= 10; ++y)
            for (int z = -10; z <= 10; ++z) {
                int E = cabs_(x) + cabs_(y) + cabs_(z);
                if (E <= 10)
                    g.v[s++] = (x + 10) | ((y + 10) << 5) | ((z + 10) << 10) | (E << 15);
            }
    return g;
}
__device__ constexpr GTab G = make_gtab();

__device__ __forceinline__ uint32_t smem_u32(const void* p) {
    uint32_t a;
    asm("{ .reg .u64 t; cvta.to.shared.u64 t, %1; cvt.u32.u64 %0, t; }"
        : "=r"(a) : "l"(p));
    return a;
}

__device__ __forceinline__ uint32_t mapa_peer(uint32_t local, uint32_t rank) {
    uint32_t r;
    asm("mapa.shared::cluster.u32 %0, %1, %2;" : "=r"(r) : "r"(local), "r"(rank));
    return r;
}

__device__ __forceinline__ float4 lds_cluster4(uint32_t addr) {
    float4 v;
    asm volatile("ld.shared::cluster.v4.f32 {%0,%1,%2,%3}, [%4];"
                 : "=f"(v.x), "=f"(v.y), "=f"(v.z), "=f"(v.w) : "r"(addr));
    return v;
}

__global__ __launch_bounds__(NTH, 2) __cluster_dims__(2, 1, 1)
void rir_half_kernel(const float* __restrict__ in, float* __restrict__ out, int write_toa)
{
    extern __shared__ float smem[];
    float*  rir_s  = smem;                           // NS * COPYLEN
    float4* params = (float4*)(smem + NS * COPYLEN); // up to NHALF float4

    const int bx  = blockIdx.x;
    const int b   = bx >> 1;
    const int h   = bx & 1;            // == cluster rank
    const int tid = threadIdx.x;
    const int sub = tid >> 7;
    const int t   = tid & 127;

    // zero private copies (16B vectorized)
    {
        float4* z = (float4*)rir_s;
        for (int p = tid; p < NS * COPYLEN / 4; p += NTH)
            z[p] = make_float4(0.f, 0.f, 0.f, 0.f);
    }

    // ---- phase 1: params for this half's images ----
    const float* ip = in + b * 10;
    const float rx = ip[0], ry = ip[1], rz = ip[2];
    const float mx = ip[3] * rx, my = ip[4] * ry, mz = ip[5] * rz;
    const float sx = ip[6] * rx, sy = ip[7] * ry, sz = ip[8] * rz;
    const float ltr = __log2f(sqrtf(1.0f - ip[9]));
    const float PI_F = 3.14159265358979323846f;

    const int s0 = h * NHALF;
    const int nh = (h == 0) ? NHALF : (NIMG - NHALF);

    for (int sl = tid; sl < nh; sl += NTH) {
        const int pk = G.v[s0 + sl];
        const int gx = (pk & 31) - 10;
        const int gy = ((pk >> 5) & 31) - 10;
        const int gz = ((pk >> 10) & 31) - 10;
        const int E  = pk >> 15;

        const float ix = (gx & 1) ? (rx * (float)(gx + 1) - sx) : (rx * (float)gx + sx);
        const float iy = (gy & 1) ? (ry * (float)(gy + 1) - sy) : (ry * (float)gy + sy);
        const float iz = (gz & 1) ? (rz * (float)(gz + 1) - sz) : (rz * (float)gz + sz);

        const float dx = ix - mx, dy = iy - my, dz = iz - mz;
        const float dist = sqrtf(dx * dx + dy * dy + dz * dz);

        const float amp   = __fdividef(exp2f((float)E * ltr), dist);
        const float delay = dist * (16000.0f / 343.0f);
        const float di    = ceilf(delay);
        float frac = fmaxf(di - delay, 1e-9f);       // exact; clamp kills x==0
        const int dii = (int)di;
        int a = dii - PADK;
        float q = ((dii & 1) ? -amp : amp) * sinpif(frac) * (1.0f / PI_F);
        if (a >= RIRLEN) { a = RIRLEN; q = 0.0f; }   // zero taps land in upper pad

        params[sl] = make_float4(q, frac, __int_as_float(a * 4), 0.0f);
    }

    if (tid == 0 && h == 0 && write_toa) {
        const float ddx = mx - sx, ddy = my - sy, ddz = mz - sz;
        out[NBATCH * RIRLEN + b] =
            40.0f + sqrtf(ddx * ddx + ddy * ddy + ddz * ddz) * (16000.0f / 343.0f);
    }
    __syncthreads();

    // ---- phase 2: single-predicate byte-space accumulation ----
    const int CH = (NHALF + NS - 1) / NS;            // 261
    const int i0 = sub * CH;
    const int i1 = (i0 + CH < nh) ? (i0 + CH) : nh;
    char* myrir_b = (char*)(rir_s + sub * COPYLEN + LOWPAD);
    const int t4 = t * 4;
    const float PI40 = 0.07853981633974483f;

    #pragma unroll 4
    for (int i = i0; i < i1; ++i) {
        const float4 p = params[i];                   // broadcast LDS.128
        const int a4 = __float_as_int(p.z);
        const int jb = (t4 - a4) & 508;               // 4*j, j = (t-a) mod 128
        const float x  = fmaf((float)jb, 0.25f, -40.0f) + p.y;  // (j-40)+frac, never 0
        const float hv = 0.5f + 0.5f * __cosf(x * PI40);        // hann
        const float v  = __fdividef(p.x, x) * hv;               // q/x * hann
        if (jb < 320) {                               // j < 80 (predicated RMW)
            float* ap = (float*)(myrir_b + a4 + jb);
            *ap += v;
        }
    }
    __syncthreads();

    // ---- phase 3a: reduce NS copies into copy 0 (vectorized) ----
    {
        float4* c0 = (float4*)(rir_s + LOWPAD);
        const float4* c1 = (const float4*)(rir_s + COPYLEN + LOWPAD);
        const float4* c2 = (const float4*)(rir_s + 2 * COPYLEN + LOWPAD);
        for (int i = tid; i < RIRLEN / 4; i += NTH) {
            float4 a = c0[i], u = c1[i], w = c2[i];
            a.x += u.x + w.x; a.y += u.y + w.y;
            a.z += u.z + w.z; a.w += u.w + w.w;
            c0[i] = a;
        }
    }

    // ---- cluster barrier: copy 0 of both CTAs visible cluster-wide ----
    asm volatile("barrier.cluster.arrive.aligned;" ::: "memory");
    asm volatile("barrier.cluster.wait.aligned;"   ::: "memory");

    // ---- phase 3b: this CTA writes samples [h*4000, h*4000+4000) ----
    {
        const int base = h * (RIRLEN / 2);                    // in floats
        const uint32_t own_base  = smem_u32(rir_s + LOWPAD + base);
        const uint32_t peer_base = mapa_peer(own_base, (uint32_t)(h ^ 1));
        float* orow = out + (size_t)b * RIRLEN + base;

        for (int i = tid; i < RIRLEN / 8; i += NTH) {         // 1000 float4 groups
            const uint32_t off = (uint32_t)i * 16u;
            float4 a;
            asm volatile("ld.shared.v4.f32 {%0,%1,%2,%3}, [%4];"
                         : "=f"(a.x), "=f"(a.y), "=f"(a.z), "=f"(a.w)
                         : "r"(own_base + off));
            const float4 c = lds_cluster4(peer_base + off);
            // sign (-1)^pos: base even, groups of 4 -> pattern + - + -
            float4 r;
            r.x =  (a.x + c.x);
            r.y = -(a.y + c.y);
            r.z =  (a.z + c.z);
            r.w = -(a.w + c.w);
            ((float4*)orow)[i] = r;
        }
    }

    // ---- REQUIRED: no CTA may exit while its peer still reads its SMEM ----
    asm volatile("barrier.cluster.arrive.aligned;" ::: "memory");
    asm volatile("barrier.cluster.wait.aligned;"   ::: "memory");
}

extern "C" void kernel_launch(void* const* d_in, const int* in_sizes, int n_in,
                              void* d_out, int out_size)
{
    const float* in  = (const float*)d_in[0];
    float*       out = (float*)d_out;
    const int write_toa = (out_size >= NBATCH * RIRLEN + NBATCH) ? 1 : 0;

    const int smem_bytes = NS * COPYLEN * 4 + NHALF * 16;   // 99072 + 12496 = 111568
    cudaFuncSetAttribute(rir_half_kernel,
                         cudaFuncAttributeMaxDynamicSharedMemorySize, smem_bytes);

    rir_half_kernel<<<2 * NBATCH, NTH, smem_bytes>>>(in, out, write_toa);
}